// round 14
// baseline (speedup 1.0000x reference)
#include <cuda_runtime.h>
#include <cuda_fp16.h>
#include <cstdint>

#define BB 4
#define SS 2048
#define DD 1024
#define MTOT (BB*SS)   // 8192

// Static device scratch
__device__ __half g_X [(long)MTOT*DD];
__device__ __half g_Y [(long)MTOT*DD];
__device__ __half g_Z [(long)MTOT*DD];
__device__ __half g_W [3][(long)DD*DD];
__device__ __half g_Q [(long)MTOT*DD];
__device__ __half g_K [(long)MTOT*DD];
__device__ __half g_Vt[(long)BB*DD*SS];    // V transposed: [b][d][s]
__device__ __half g_P [(long)BB*SS*SS];    // exp(scores) fp16 (unnormalized)
__device__ float  g_RS[MTOT];              // per-row sums of exp

// Scheduler state. Statically zero-initialized; the LAST exiting CTA resets
// everything at kernel end, so each graph replay starts clean.
__device__ int g_tick;
__device__ int g_done;
__device__ int g_cv[216];  // conversion-done flags (64 X, 64 Y, 64 Z, 24 W)
__device__ int g_qc[64];   // Q proj tiles done per 128-row block (need 8)
__device__ int g_kc[64];   // K proj tiles done per 128-row block (need 8)
__device__ int g_sc[64];   // score tiles done per 128-row block (need 16)
__device__ int g_vc[32];   // V proj tiles done per (batch, d-block) (need 16)

// Ticket layout
#define NCVT  216
#define T_PROJ   216     // +1536
#define T_SC     1752    // +1024
#define T_PV     2776    // +512
#define T_END    3288

// ---------------------------------------------------------------------------
// helpers
// ---------------------------------------------------------------------------
__device__ __forceinline__ uint32_t smem_u32(const void* p) {
    uint32_t a;
    asm("{ .reg .u64 t; cvta.to.shared.u64 t, %1; cvt.u32.u64 %0, t; }"
        : "=r"(a) : "l"(p));
    return a;
}
__device__ __forceinline__ void cp16(uint32_t s, const void* g) {
    asm volatile("cp.async.cg.shared.global [%0], [%1], 16;" :: "r"(s), "l"(g));
}

#define LDSM4(r, addr) \
    asm volatile("ldmatrix.sync.aligned.m8n8.x4.shared.b16 {%0,%1,%2,%3}, [%4];" \
        : "=r"((r)[0]), "=r"((r)[1]), "=r"((r)[2]), "=r"((r)[3]) : "r"(addr))

#define MMA_F16(c, a, b0, b1) \
    asm volatile("mma.sync.aligned.m16n8k16.row.col.f32.f16.f16.f32 " \
        "{%0,%1,%2,%3}, {%4,%5,%6,%7}, {%8,%9}, {%0,%1,%2,%3};" \
        : "+f"((c)[0]), "+f"((c)[1]), "+f"((c)[2]), "+f"((c)[3]) \
        : "r"((a)[0]), "r"((a)[1]), "r"((a)[2]), "r"((a)[3]), "r"(b0), "r"(b1))

// ---------------------------------------------------------------------------
// fp16 NT GEMM mainloop (SW128, rolling fragment prefetch, hoisted XOR).
// Entry __syncthreads protects smem reuse across tiles AND doubles as the
// rendezvous for the tid-0 dependency spin (cp.async only after it).
// ---------------------------------------------------------------------------
__device__ __forceinline__ void mainloop_h(
    const __half* __restrict__ A, const __half* __restrict__ B,
    int K, int lda, int ldb, uint32_t sbase,
    int tid, int lane, int wm, int wn, float acc[4][4][4])
{
    constexpr int STAGES = 3;
    constexpr uint32_t STG_BYTES = 32768;

    const __half* ga[4];
    const __half* gb[4];
    uint32_t sw[4];
#pragma unroll
    for (int i = 0; i < 4; i++) {
        const int idx = i * 256 + tid;
        const int row = idx >> 3;
        const int c   = idx & 7;
        const uint32_t off = (uint32_t)row * 128u + (uint32_t)c * 16u;
        sw[i] = off ^ ((off >> 3) & 0x70u);
        ga[i] = A + (long)row * lda + c * 8;
        gb[i] = B + (long)row * ldb + c * 8;
    }

    auto issue = [&](int kt, int st) {
        const uint32_t s0 = sbase + (uint32_t)st * STG_BYTES;
#pragma unroll
        for (int i = 0; i < 4; i++) cp16(s0 + sw[i], ga[i] + (long)kt * 64);
#pragma unroll
        for (int i = 0; i < 4; i++) cp16(s0 + 16384u + sw[i], gb[i] + (long)kt * 64);
        asm volatile("cp.async.commit_group;" ::: "memory");
    };

    const int r16 = lane & 15;
    const uint32_t hi16 = (uint32_t)(lane >> 4) * 16u;
    const uint32_t x = ((uint32_t)(lane & 7)) << 4;
    uint32_t kbx[4];
#pragma unroll
    for (int kc = 0; kc < 4; kc++) kbx[kc] = ((uint32_t)kc * 32u + hi16) ^ x;

    uint32_t aBase[4], bBase[2];
#pragma unroll
    for (int mt = 0; mt < 4; mt++)
        aBase[mt] = (uint32_t)(wm * 64 + mt * 16 + r16) * 128u;
#pragma unroll
    for (int p = 0; p < 2; p++)
        bBase[p] = 16384u + (uint32_t)(wn * 32 + p * 16 + r16) * 128u;

    __syncthreads();   // smem safe + deps satisfied (tid 0 arrived)

    const int KT = K >> 6;
#pragma unroll
    for (int s = 0; s < STAGES - 1; s++) issue(s, s);

    for (int kt = 0; kt < KT; kt++) {
        asm volatile("cp.async.wait_group %0;" :: "n"(STAGES - 2));
        __syncthreads();

        const int pf = kt + STAGES - 1;
        if (pf < KT) issue(pf, pf % STAGES);
        else asm volatile("cp.async.commit_group;" ::: "memory");

        const uint32_t base = sbase + (uint32_t)(kt % STAGES) * STG_BYTES;

        uint32_t af[2][4];
        uint32_t bf[2][2][4];

        LDSM4(bf[0][0], base + bBase[0] + kbx[0]);
        LDSM4(bf[0][1], base + bBase[1] + kbx[0]);
        LDSM4(af[0],    base + aBase[0] + kbx[0]);

#pragma unroll
        for (int kc = 0; kc < 4; kc++) {
#pragma unroll
            for (int mt = 0; mt < 4; mt++) {
                if (mt < 3) {
                    LDSM4(af[(mt + 1) & 1], base + aBase[mt + 1] + kbx[kc]);
                } else if (kc < 3) {
                    LDSM4(bf[(kc + 1) & 1][0], base + bBase[0] + kbx[kc + 1]);
                    LDSM4(bf[(kc + 1) & 1][1], base + bBase[1] + kbx[kc + 1]);
                    LDSM4(af[0],               base + aBase[0] + kbx[kc + 1]);
                }
#pragma unroll
                for (int nt = 0; nt < 4; nt++)
                    MMA_F16(acc[mt][nt], af[mt & 1],
                            bf[kc & 1][nt >> 1][nt & 1],
                            bf[kc & 1][nt >> 1][(nt & 1) + 2]);
            }
        }
    }
}

// ---------------------------------------------------------------------------
// Persistent mega-kernel.
// Tickets: 0-215 conversion (X/Y/Z blocks + W blocks; X tickets zero RS rows)
//          216-1751 projections, 1752-2775 scores, 2776-3287 PV.
// All gates depend only on strictly lower tickets -> deadlock-free.
// Last exiting CTA resets scheduler state for the next graph replay.
// ---------------------------------------------------------------------------
__global__ __launch_bounds__(256, 2)
void attn_mega(const float4* __restrict__ xf, const float4* __restrict__ yf,
               const float4* __restrict__ zf, const float4* __restrict__ wqf,
               const float4* __restrict__ wkf, const float4* __restrict__ wvf,
               const float* __restrict__ bq, const float* __restrict__ bk,
               const float* __restrict__ bv,
               __half* __restrict__ X, __half* __restrict__ Y,
               __half* __restrict__ Z, __half* __restrict__ W,
               __half* __restrict__ Q, __half* __restrict__ Kb,
               __half* __restrict__ Vt, __half* __restrict__ P,
               float* __restrict__ RS, float* __restrict__ O)
{
    extern __shared__ __align__(1024) char smem[];
    __shared__ int s_t;
    const uint32_t sbase = smem_u32(smem);
    const int tid  = threadIdx.x;
    const int lane = tid & 31;
    const int wid  = tid >> 5;
    const int wm   = wid & 1;
    const int wn   = wid >> 1;
    const int g    = lane >> 2;
    const int tg   = lane & 3;

    for (;;) {
        if (tid == 0) s_t = atomicAdd(&g_tick, 1);
        __syncthreads();
        const int t = s_t;
        if (t >= T_END) break;

        if (t < NCVT) {
            // ---------------- conversion ticket (128x1024 block) ----------------
            const float4* in;
            __half* out;
            if (t < 64) {
                in = xf + (long)t * 32768;  out = X + (long)t * 131072;
                if (tid < 128) RS[t * 128 + tid] = 0.0f;
            } else if (t < 128) {
                in = yf + (long)(t - 64) * 32768;  out = Y + (long)(t - 64) * 131072;
            } else if (t < 192) {
                in = zf + (long)(t - 128) * 32768; out = Z + (long)(t - 128) * 131072;
            } else {
                const int w  = t - 192;
                const int wz = w >> 3, bn = w & 7;
                in  = ((wz == 0) ? wqf : (wz == 1) ? wkf : wvf) + (long)bn * 32768;
                out = W + (long)wz * 1048576 + (long)bn * 131072;
            }
#pragma unroll 4
            for (int it = 0; it < 64; it++) {
                const int e = it * 2048 + tid * 8;
                float4 a0 = in[(e >> 2)];
                float4 a1 = in[(e >> 2) + 1];
                __half2 h[4];
                h[0] = __floats2half2_rn(a0.x, a0.y);
                h[1] = __floats2half2_rn(a0.z, a0.w);
                h[2] = __floats2half2_rn(a1.x, a1.y);
                h[3] = __floats2half2_rn(a1.z, a1.w);
                *(uint4*)(out + e) = *(uint4*)h;
            }
            __threadfence();
            __syncthreads();
            if (tid == 0) atomicExch(&g_cv[t], 1);
            continue;
        }

        float acc[4][4][4];
#pragma unroll
        for (int mt = 0; mt < 4; mt++)
#pragma unroll
            for (int nt = 0; nt < 4; nt++)
#pragma unroll
                for (int i = 0; i < 4; i++) acc[mt][nt][i] = 0.0f;

        if (t < T_SC) {
            // ---------------- projection tile ----------------
            const int pt  = t - T_PROJ;
            const int z   = pt >> 9;
            const int rem = pt & 511;
            const int bmb = rem >> 3;
            const int bnb = rem & 7;
            if (tid == 0) {
                while (atomicAdd(&g_cv[z * 64 + bmb], 0) == 0) __nanosleep(128);
                while (atomicAdd(&g_cv[192 + z * 8 + bnb], 0) == 0) __nanosleep(128);
                __threadfence();
            }
            const int bm = bmb * 128;
            const int bn = bnb * 128;
            const __half* A = ((z == 0) ? X : (z == 1) ? Y : Z) + (long)bm * DD;
            const __half* B = W + (long)z * DD * DD + (long)bn * DD;
            mainloop_h(A, B, DD, DD, DD, sbase, tid, lane, wm, wn, acc);

            const float* bias = (z == 0) ? bq : (z == 1) ? bk : bv;
#pragma unroll
            for (int mt = 0; mt < 4; mt++) {
#pragma unroll
                for (int nt = 0; nt < 4; nt++) {
                    const int n = bn + wn * 32 + nt * 8 + tg * 2;
                    float2 bv2 = *(const float2*)(bias + n);
#pragma unroll
                    for (int h = 0; h < 2; h++) {
                        const int m = bm + wm * 64 + mt * 16 + g + h * 8;
                        const float v0 = acc[mt][nt][h * 2 + 0] + bv2.x;
                        const float v1 = acc[mt][nt][h * 2 + 1] + bv2.y;
                        if (z == 2) {
                            const int b = m >> 11;
                            const int s = m & (SS - 1);
                            const long o = ((long)b * DD + n) * SS + s;
                            Vt[o]      = __float2half_rn(v0);
                            Vt[o + SS] = __float2half_rn(v1);
                        } else {
                            __half* C = (z == 0) ? Q : Kb;
                            *(__half2*)(C + (long)m * DD + n) = __floats2half2_rn(v0, v1);
                        }
                    }
                }
            }
            __threadfence();
            __syncthreads();
            if (tid == 0) {
                if (z == 0)      atomicAdd(&g_qc[bmb], 1);
                else if (z == 1) atomicAdd(&g_kc[bmb], 1);
                else             atomicAdd(&g_vc[(bmb >> 4) * 8 + bnb], 1);
            }
        } else if (t < T_PV) {
            // ---------------- scores tile ----------------
            const int s   = t - T_SC;
            const int bz  = s >> 8;
            const int bml = (s >> 4) & 15;
            const int bnl = s & 15;
            if (tid == 0) {
                while (atomicAdd(&g_qc[bz * 16 + bml], 0) < 8) __nanosleep(128);
                while (atomicAdd(&g_kc[bz * 16 + bnl], 0) < 8) __nanosleep(128);
                __threadfence();
            }
            const int bm = bml * 128;
            const int bn = bnl * 128;
            const __half* A = Q  + (long)bz * SS * DD + (long)bm * DD;
            const __half* B = Kb + (long)bz * SS * DD + (long)bn * DD;
            mainloop_h(A, B, DD, DD, DD, sbase, tid, lane, wm, wn, acc);

            __half* Pb = P + (long)bz * SS * SS;
            float* rs = RS + bz * SS;
#pragma unroll
            for (int mt = 0; mt < 4; mt++) {
                float s0 = 0.0f, s1 = 0.0f;
                const int m0 = bm + wm * 64 + mt * 16 + g;
#pragma unroll
                for (int nt = 0; nt < 4; nt++) {
                    const int n = bn + wn * 32 + nt * 8 + tg * 2;
                    const float e00 = __expf(acc[mt][nt][0] * 0.03125f);
                    const float e01 = __expf(acc[mt][nt][1] * 0.03125f);
                    const float e10 = __expf(acc[mt][nt][2] * 0.03125f);
                    const float e11 = __expf(acc[mt][nt][3] * 0.03125f);
                    s0 += e00 + e01;
                    s1 += e10 + e11;
                    *(__half2*)(Pb + (long)m0 * SS + n)       = __floats2half2_rn(e00, e01);
                    *(__half2*)(Pb + (long)(m0 + 8) * SS + n) = __floats2half2_rn(e10, e11);
                }
                s0 += __shfl_xor_sync(~0u, s0, 1);
                s0 += __shfl_xor_sync(~0u, s0, 2);
                s1 += __shfl_xor_sync(~0u, s1, 1);
                s1 += __shfl_xor_sync(~0u, s1, 2);
                if (tg == 0) {
                    atomicAdd(&rs[m0],     s0);
                    atomicAdd(&rs[m0 + 8], s1);
                }
            }
            __threadfence();
            __syncthreads();
            if (tid == 0) atomicAdd(&g_sc[bz * 16 + bml], 1);
        } else {
            // ---------------- PV tile ----------------
            const int p   = t - T_PV;
            const int bz  = p >> 7;
            const int bml = (p >> 3) & 15;
            const int bnl = p & 7;
            if (tid == 0) {
                while (atomicAdd(&g_sc[bz * 16 + bml], 0) < 16) __nanosleep(128);
                while (atomicAdd(&g_vc[bz * 8 + bnl],  0) < 16) __nanosleep(128);
                __threadfence();
            }
            const int bm = bml * 128;
            const int bn = bnl * 128;
            const __half* A = P  + (long)bz * SS * SS + (long)bm * SS;
            const __half* B = Vt + (long)bz * DD * SS + (long)bn * SS;
            mainloop_h(A, B, SS, SS, SS, sbase, tid, lane, wm, wn, acc);

            const float* rs = RS + bz * SS;
            float* C = O + (long)bz * SS * DD;
#pragma unroll
            for (int mt = 0; mt < 4; mt++) {
                const int m0 = bm + wm * 64 + mt * 16 + g;
                const float i0 = 1.0f / __ldg(&rs[m0]);
                const float i1 = 1.0f / __ldg(&rs[m0 + 8]);
#pragma unroll
                for (int nt = 0; nt < 4; nt++) {
                    const int n = bn + wn * 32 + nt * 8 + tg * 2;
                    float2 v0, v1;
                    v0.x = acc[mt][nt][0] * i0;
                    v0.y = acc[mt][nt][1] * i0;
                    v1.x = acc[mt][nt][2] * i1;
                    v1.y = acc[mt][nt][3] * i1;
                    *(float2*)(C + (long)m0 * DD + n)       = v0;
                    *(float2*)(C + (long)(m0 + 8) * DD + n) = v1;
                }
            }
        }
    }

    // ---- replay-safe scheduler reset by the last exiting CTA ----
    __syncthreads();
    if (tid == 0) {
        const int d = atomicAdd(&g_done, 1);
        if (d == (int)gridDim.x - 1) {
            g_tick = 0;
            g_done = 0;
            for (int i = 0; i < 216; i++) g_cv[i] = 0;
            for (int i = 0; i < 64; i++) { g_qc[i] = 0; g_kc[i] = 0; g_sc[i] = 0; }
            for (int i = 0; i < 32; i++) g_vc[i] = 0;
            __threadfence();
        }
    }
}

extern "C" void kernel_launch(void* const* d_in, const int* in_sizes, int n_in,
                              void* d_out, int out_size)
{
    const float* x  = (const float*)d_in[0];
    const float* y  = (const float*)d_in[1];
    const float* z  = (const float*)d_in[2];
    const float* Wq = (const float*)d_in[3];
    const float* bq = (const float*)d_in[4];
    const float* Wk = (const float*)d_in[5];
    const float* bk = (const float*)d_in[6];
    const float* Wv = (const float*)d_in[7];
    const float* bv = (const float*)d_in[8];
    float* out = (float*)d_out;

    void *pX, *pY, *pZ, *pW, *pQ, *pK, *pV, *pP, *pRS;
    cudaGetSymbolAddress(&pX,  g_X);
    cudaGetSymbolAddress(&pY,  g_Y);
    cudaGetSymbolAddress(&pZ,  g_Z);
    cudaGetSymbolAddress(&pW,  g_W);
    cudaGetSymbolAddress(&pQ,  g_Q);
    cudaGetSymbolAddress(&pK,  g_K);
    cudaGetSymbolAddress(&pV,  g_Vt);
    cudaGetSymbolAddress(&pP,  g_P);
    cudaGetSymbolAddress(&pRS, g_RS);

    int nsm = 148;
    cudaDeviceGetAttribute(&nsm, cudaDevAttrMultiProcessorCount, 0);

    const int SMEMSZ = 3 * 32768;   // 96 KB
    cudaFuncSetAttribute(attn_mega, cudaFuncAttributeMaxDynamicSharedMemorySize, SMEMSZ);

    attn_mega<<<2 * nsm, 256, SMEMSZ>>>(
        (const float4*)x, (const float4*)y, (const float4*)z,
        (const float4*)Wq, (const float4*)Wk, (const float4*)Wv,
        bq, bk, bv,
        (__half*)pX, (__half*)pY, (__half*)pZ, (__half*)pW,
        (__half*)pQ, (__half*)pK, (__half*)pV, (__half*)pP,
        (float*)pRS, out);
}

// round 15
// speedup vs baseline: 1.0260x; 1.0260x over previous
#include <cuda_runtime.h>
#include <cuda_fp16.h>
#include <cstdint>

#define BB 4
#define SS 2048
#define DD 1024
#define MTOT (BB*SS)   // 8192

// Static device scratch
__device__ __half g_X [(long)MTOT*DD];
__device__ __half g_Y [(long)MTOT*DD];
__device__ __half g_Z [(long)MTOT*DD];
__device__ __half g_W [3][(long)DD*DD];
__device__ __half g_Q [(long)MTOT*DD];
__device__ __half g_K [(long)MTOT*DD];
__device__ __half g_Vt[(long)BB*DD*SS];    // V transposed: [b][d][s]
__device__ __half g_P [(long)BB*SS*SS];    // exp(scores) fp16 (unnormalized)
__device__ float  g_RS[MTOT];              // per-row sums of exp

// Scheduling state (zeroed by cvt_all each call -> replay-safe)
__device__ int g_tick;
__device__ int g_qc[64];   // Q proj tiles done per 128-row block (need 8)
__device__ int g_kc[64];   // K proj tiles done per 128-row block (need 8)
__device__ int g_sc[64];   // score tiles done per 128-row block (need 16)
__device__ int g_vc[32];   // V proj tiles done per (batch, d-block) (need 16)

// ---------------------------------------------------------------------------
// helpers
// ---------------------------------------------------------------------------
__device__ __forceinline__ uint32_t smem_u32(const void* p) {
    uint32_t a;
    asm("{ .reg .u64 t; cvta.to.shared.u64 t, %1; cvt.u32.u64 %0, t; }"
        : "=r"(a) : "l"(p));
    return a;
}
__device__ __forceinline__ void cp16(uint32_t s, const void* g) {
    asm volatile("cp.async.cg.shared.global [%0], [%1], 16;" :: "r"(s), "l"(g));
}

#define LDSM4(r, addr) \
    asm volatile("ldmatrix.sync.aligned.m8n8.x4.shared.b16 {%0,%1,%2,%3}, [%4];" \
        : "=r"((r)[0]), "=r"((r)[1]), "=r"((r)[2]), "=r"((r)[3]) : "r"(addr))

#define MMA_F16(c, a, b0, b1) \
    asm volatile("mma.sync.aligned.m16n8k16.row.col.f32.f16.f16.f32 " \
        "{%0,%1,%2,%3}, {%4,%5,%6,%7}, {%8,%9}, {%0,%1,%2,%3};" \
        : "+f"((c)[0]), "+f"((c)[1]), "+f"((c)[2]), "+f"((c)[3]) \
        : "r"((a)[0]), "r"((a)[1]), "r"((a)[2]), "r"((a)[3]), "r"(b0), "r"(b1))

// fp16-accumulator variant: D,C are 2 regs of f16x2
#define MMA_F16ACC(c2, a, b0, b1) \
    asm volatile("mma.sync.aligned.m16n8k16.row.col.f16.f16.f16.f16 " \
        "{%0,%1}, {%2,%3,%4,%5}, {%6,%7}, {%0,%1};" \
        : "+r"((c2)[0]), "+r"((c2)[1]) \
        : "r"((a)[0]), "r"((a)[1]), "r"((a)[2]), "r"((a)[3]), "r"(b0), "r"(b1))

// ---------------------------------------------------------------------------
// Fused fp32->fp16 conversion for X,Y,Z,Wq,Wk,Wv + RS/scheduler zeroing.
// ---------------------------------------------------------------------------
__global__ void cvt_all(const float4* __restrict__ x, const float4* __restrict__ y,
                        const float4* __restrict__ z, const float4* __restrict__ wq,
                        const float4* __restrict__ wk, const float4* __restrict__ wv,
                        __half* __restrict__ X, __half* __restrict__ Y,
                        __half* __restrict__ Z, __half* __restrict__ W,
                        float* __restrict__ rs)
{
    const int b = blockIdx.x;
    const int tid = threadIdx.x;

    if (b < 32) rs[b * 256 + tid] = 0.0f;
    if (b == 0) {
        if (tid == 0) g_tick = 0;
        else if (tid < 65)  g_qc[tid - 1]   = 0;
        else if (tid < 129) g_kc[tid - 65]  = 0;
        else if (tid < 193) g_sc[tid - 129] = 0;
        else if (tid < 225) g_vc[tid - 193] = 0;
    }

    const float4* in;
    __half* out;
    long base;
    if (b < 4096)       { in = x;  out = X; base = (long)b * 2048; }
    else if (b < 8192)  { in = y;  out = Y; base = (long)(b - 4096) * 2048; }
    else if (b < 12288) { in = z;  out = Z; base = (long)(b - 8192) * 2048; }
    else if (b < 12800) { in = wq; out = W;                       base = (long)(b - 12288) * 2048; }
    else if (b < 13312) { in = wk; out = W + (long)DD * DD;       base = (long)(b - 12800) * 2048; }
    else                { in = wv; out = W + 2 * (long)DD * DD;   base = (long)(b - 13312) * 2048; }

    const long e = base + (long)tid * 8;
    float4 a0 = in[e >> 2], a1 = in[(e >> 2) + 1];
    __half2 h[4];
    h[0] = __floats2half2_rn(a0.x, a0.y);
    h[1] = __floats2half2_rn(a0.z, a0.w);
    h[2] = __floats2half2_rn(a1.x, a1.y);
    h[3] = __floats2half2_rn(a1.z, a1.w);
    *(uint4*)(out + e) = *(uint4*)h;
}

// ---------------------------------------------------------------------------
// Common smem-pipeline prologue data
// ---------------------------------------------------------------------------
struct PipeCtx {
    const __half* ga[4];
    const __half* gb[4];
    uint32_t sw[4];
    uint32_t kbx[4];
    uint32_t aBase[4], bBase[2];
};

__device__ __forceinline__ void pipe_setup(
    PipeCtx& c, const __half* A, const __half* B, int lda, int ldb,
    int tid, int lane, int wm, int wn)
{
#pragma unroll
    for (int i = 0; i < 4; i++) {
        const int idx = i * 256 + tid;
        const int row = idx >> 3;
        const int ch  = idx & 7;
        const uint32_t off = (uint32_t)row * 128u + (uint32_t)ch * 16u;
        c.sw[i] = off ^ ((off >> 3) & 0x70u);
        c.ga[i] = A + (long)row * lda + ch * 8;
        c.gb[i] = B + (long)row * ldb + ch * 8;
    }
    const int r16 = lane & 15;
    const uint32_t hi16 = (uint32_t)(lane >> 4) * 16u;
    const uint32_t x = ((uint32_t)(lane & 7)) << 4;
#pragma unroll
    for (int kc = 0; kc < 4; kc++) c.kbx[kc] = ((uint32_t)kc * 32u + hi16) ^ x;
#pragma unroll
    for (int mt = 0; mt < 4; mt++)
        c.aBase[mt] = (uint32_t)(wm * 64 + mt * 16 + r16) * 128u;
#pragma unroll
    for (int p = 0; p < 2; p++)
        c.bBase[p] = 16384u + (uint32_t)(wn * 32 + p * 16 + r16) * 128u;
}

#define PIPE_ISSUE(c, kt, st, sbase) do { \
    const uint32_t s0_ = (sbase) + (uint32_t)(st) * 32768u; \
    _Pragma("unroll") \
    for (int i_ = 0; i_ < 4; i_++) cp16(s0_ + (c).sw[i_], (c).ga[i_] + (long)(kt) * 64); \
    _Pragma("unroll") \
    for (int i_ = 0; i_ < 4; i_++) cp16(s0_ + 16384u + (c).sw[i_], (c).gb[i_] + (long)(kt) * 64); \
    asm volatile("cp.async.commit_group;" ::: "memory"); \
} while (0)

// ---------------------------------------------------------------------------
// fp16 NT GEMM mainloop, f32 accumulators (SW128, rolling prefetch).
// ---------------------------------------------------------------------------
__device__ __forceinline__ void mainloop_h(
    const __half* __restrict__ A, const __half* __restrict__ B,
    int K, int lda, int ldb, uint32_t sbase,
    int tid, int lane, int wm, int wn, float acc[4][4][4])
{
    PipeCtx c;
    pipe_setup(c, A, B, lda, ldb, tid, lane, wm, wn);
    __syncthreads();
    const int KT = K >> 6;
    PIPE_ISSUE(c, 0, 0, sbase);
    PIPE_ISSUE(c, 1, 1, sbase);

    for (int kt = 0; kt < KT; kt++) {
        asm volatile("cp.async.wait_group %0;" :: "n"(1));
        __syncthreads();
        const int pf = kt + 2;
        if (pf < KT) PIPE_ISSUE(c, pf, pf % 3, sbase);
        else asm volatile("cp.async.commit_group;" ::: "memory");

        const uint32_t base = sbase + (uint32_t)(kt % 3) * 32768u;
        uint32_t af[2][4];
        uint32_t bf[2][2][4];
        LDSM4(bf[0][0], base + c.bBase[0] + c.kbx[0]);
        LDSM4(bf[0][1], base + c.bBase[1] + c.kbx[0]);
        LDSM4(af[0],    base + c.aBase[0] + c.kbx[0]);

#pragma unroll
        for (int kc = 0; kc < 4; kc++) {
#pragma unroll
            for (int mt = 0; mt < 4; mt++) {
                if (mt < 3) {
                    LDSM4(af[(mt + 1) & 1], base + c.aBase[mt + 1] + c.kbx[kc]);
                } else if (kc < 3) {
                    LDSM4(bf[(kc + 1) & 1][0], base + c.bBase[0] + c.kbx[kc + 1]);
                    LDSM4(bf[(kc + 1) & 1][1], base + c.bBase[1] + c.kbx[kc + 1]);
                    LDSM4(af[0],               base + c.aBase[0] + c.kbx[kc + 1]);
                }
#pragma unroll
                for (int nt = 0; nt < 4; nt++)
                    MMA_F16(acc[mt][nt], af[mt & 1],
                            bf[kc & 1][nt >> 1][nt & 1],
                            bf[kc & 1][nt >> 1][(nt & 1) + 2]);
            }
        }
    }
}

// ---------------------------------------------------------------------------
// fp16 NT GEMM mainloop, f16 ACCUMULATORS (scores only). acc2[4][4][2] f16x2.
// ---------------------------------------------------------------------------
__device__ __forceinline__ void mainloop_s(
    const __half* __restrict__ A, const __half* __restrict__ B,
    int K, int lda, int ldb, uint32_t sbase,
    int tid, int lane, int wm, int wn, uint32_t acc2[4][4][2])
{
    PipeCtx c;
    pipe_setup(c, A, B, lda, ldb, tid, lane, wm, wn);
    __syncthreads();
    const int KT = K >> 6;
    PIPE_ISSUE(c, 0, 0, sbase);
    PIPE_ISSUE(c, 1, 1, sbase);

    for (int kt = 0; kt < KT; kt++) {
        asm volatile("cp.async.wait_group %0;" :: "n"(1));
        __syncthreads();
        const int pf = kt + 2;
        if (pf < KT) PIPE_ISSUE(c, pf, pf % 3, sbase);
        else asm volatile("cp.async.commit_group;" ::: "memory");

        const uint32_t base = sbase + (uint32_t)(kt % 3) * 32768u;
        uint32_t af[2][4];
        uint32_t bf[2][2][4];
        LDSM4(bf[0][0], base + c.bBase[0] + c.kbx[0]);
        LDSM4(bf[0][1], base + c.bBase[1] + c.kbx[0]);
        LDSM4(af[0],    base + c.aBase[0] + c.kbx[0]);

#pragma unroll
        for (int kc = 0; kc < 4; kc++) {
#pragma unroll
            for (int mt = 0; mt < 4; mt++) {
                if (mt < 3) {
                    LDSM4(af[(mt + 1) & 1], base + c.aBase[mt + 1] + c.kbx[kc]);
                } else if (kc < 3) {
                    LDSM4(bf[(kc + 1) & 1][0], base + c.bBase[0] + c.kbx[kc + 1]);
                    LDSM4(bf[(kc + 1) & 1][1], base + c.bBase[1] + c.kbx[kc + 1]);
                    LDSM4(af[0],               base + c.aBase[0] + c.kbx[kc + 1]);
                }
#pragma unroll
                for (int nt = 0; nt < 4; nt++)
                    MMA_F16ACC(acc2[mt][nt], af[mt & 1],
                               bf[kc & 1][nt >> 1][nt & 1],
                               bf[kc & 1][nt >> 1][(nt & 1) + 2]);
            }
        }
    }
}

// ---------------------------------------------------------------------------
// Persistent mega-kernel: tickets 0-511 Qproj, 512-1023 Kproj, 1024-1535
// Vproj, 1536-2559 scores (f16 accum), 2560-3071 PV (f32 accum).
// ---------------------------------------------------------------------------
__global__ __launch_bounds__(256, 2)
void attn_mega(const __half* __restrict__ X, const __half* __restrict__ Y,
               const __half* __restrict__ Z, const __half* __restrict__ W,
               const float* __restrict__ bq, const float* __restrict__ bk,
               const float* __restrict__ bv,
               __half* __restrict__ Q, __half* __restrict__ Kb,
               __half* __restrict__ Vt, __half* __restrict__ P,
               float* __restrict__ RS, float* __restrict__ O)
{
    extern __shared__ __align__(1024) char smem[];
    __shared__ int s_t;
    const uint32_t sbase = smem_u32(smem);
    const int tid  = threadIdx.x;
    const int lane = tid & 31;
    const int wid  = tid >> 5;
    const int wm   = wid & 1;
    const int wn   = wid >> 1;
    const int g    = lane >> 2;
    const int tg   = lane & 3;

    for (;;) {
        if (tid == 0) s_t = atomicAdd(&g_tick, 1);
        __syncthreads();
        const int t = s_t;
        if (t >= 3072) break;

        if (t < 1536) {
            // ---------------- projection tile (f32 accum) ----------------
            float acc[4][4][4];
#pragma unroll
            for (int mt = 0; mt < 4; mt++)
#pragma unroll
                for (int nt = 0; nt < 4; nt++)
#pragma unroll
                    for (int i = 0; i < 4; i++) acc[mt][nt][i] = 0.0f;

            const int z   = t >> 9;
            const int rem = t & 511;
            const int bm  = (rem >> 3) * 128;
            const int bn  = (rem & 7) * 128;
            const __half* A = ((z == 0) ? X : (z == 1) ? Y : Z) + (long)bm * DD;
            const __half* B = W + (long)z * DD * DD + (long)bn * DD;
            mainloop_h(A, B, DD, DD, DD, sbase, tid, lane, wm, wn, acc);

            const float* bias = (z == 0) ? bq : (z == 1) ? bk : bv;
#pragma unroll
            for (int mt = 0; mt < 4; mt++) {
#pragma unroll
                for (int nt = 0; nt < 4; nt++) {
                    const int n = bn + wn * 32 + nt * 8 + tg * 2;
                    float2 bv2 = *(const float2*)(bias + n);
#pragma unroll
                    for (int h = 0; h < 2; h++) {
                        const int m = bm + wm * 64 + mt * 16 + g + h * 8;
                        const float v0 = acc[mt][nt][h * 2 + 0] + bv2.x;
                        const float v1 = acc[mt][nt][h * 2 + 1] + bv2.y;
                        if (z == 2) {
                            const int b = m >> 11;
                            const int s = m & (SS - 1);
                            const long o = ((long)b * DD + n) * SS + s;
                            Vt[o]      = __float2half_rn(v0);
                            Vt[o + SS] = __float2half_rn(v1);
                        } else {
                            __half* C = (z == 0) ? Q : Kb;
                            *(__half2*)(C + (long)m * DD + n) = __floats2half2_rn(v0, v1);
                        }
                    }
                }
            }
            __threadfence();
            __syncthreads();
            if (tid == 0) {
                if (z == 0)      atomicAdd(&g_qc[rem >> 3], 1);
                else if (z == 1) atomicAdd(&g_kc[rem >> 3], 1);
                else             atomicAdd(&g_vc[((rem >> 3) >> 4) * 8 + (rem & 7)], 1);
            }
        } else if (t < 2560) {
            // ---------------- scores tile (f16 accum) ----------------
            uint32_t acc2[4][4][2];
#pragma unroll
            for (int mt = 0; mt < 4; mt++)
#pragma unroll
                for (int nt = 0; nt < 4; nt++) {
                    acc2[mt][nt][0] = 0u;
                    acc2[mt][nt][1] = 0u;
                }

            const int s   = t - 1536;
            const int bz  = s >> 8;
            const int bml = (s >> 4) & 15;
            const int bnl = s & 15;
            if (tid == 0) {
                while (atomicAdd(&g_qc[bz * 16 + bml], 0) < 8) __nanosleep(128);
                while (atomicAdd(&g_kc[bz * 16 + bnl], 0) < 8) __nanosleep(128);
                __threadfence();
            }
            const int bm = bml * 128;
            const int bn = bnl * 128;
            const __half* A = Q  + (long)bz * SS * DD + (long)bm * DD;
            const __half* B = Kb + (long)bz * SS * DD + (long)bn * DD;
            mainloop_s(A, B, DD, DD, DD, sbase, tid, lane, wm, wn, acc2);

            __half* Pb = P + (long)bz * SS * SS;
            float* rs = RS + bz * SS;
#pragma unroll
            for (int mt = 0; mt < 4; mt++) {
                float s0 = 0.0f, s1 = 0.0f;
                const int m0 = bm + wm * 64 + mt * 16 + g;
#pragma unroll
                for (int nt = 0; nt < 4; nt++) {
                    const int n = bn + wn * 32 + nt * 8 + tg * 2;
                    float2 f0 = __half22float2(*(__half2*)&acc2[mt][nt][0]);
                    float2 f1 = __half22float2(*(__half2*)&acc2[mt][nt][1]);
                    const float e00 = __expf(f0.x * 0.03125f);
                    const float e01 = __expf(f0.y * 0.03125f);
                    const float e10 = __expf(f1.x * 0.03125f);
                    const float e11 = __expf(f1.y * 0.03125f);
                    s0 += e00 + e01;
                    s1 += e10 + e11;
                    *(__half2*)(Pb + (long)m0 * SS + n)       = __floats2half2_rn(e00, e01);
                    *(__half2*)(Pb + (long)(m0 + 8) * SS + n) = __floats2half2_rn(e10, e11);
                }
                s0 += __shfl_xor_sync(~0u, s0, 1);
                s0 += __shfl_xor_sync(~0u, s0, 2);
                s1 += __shfl_xor_sync(~0u, s1, 1);
                s1 += __shfl_xor_sync(~0u, s1, 2);
                if (tg == 0) {
                    atomicAdd(&rs[m0],     s0);
                    atomicAdd(&rs[m0 + 8], s1);
                }
            }
            __threadfence();
            __syncthreads();
            if (tid == 0) atomicAdd(&g_sc[bz * 16 + bml], 1);
        } else {
            // ---------------- PV tile (f32 accum) ----------------
            float acc[4][4][4];
#pragma unroll
            for (int mt = 0; mt < 4; mt++)
#pragma unroll
                for (int nt = 0; nt < 4; nt++)
#pragma unroll
                    for (int i = 0; i < 4; i++) acc[mt][nt][i] = 0.0f;

            const int p   = t - 2560;
            const int bz  = p >> 7;
            const int bml = (p >> 3) & 15;
            const int bnl = p & 7;
            if (tid == 0) {
                while (atomicAdd(&g_sc[bz * 16 + bml], 0) < 16) __nanosleep(128);
                while (atomicAdd(&g_vc[bz * 8 + bnl],  0) < 16) __nanosleep(128);
                __threadfence();
            }
            const int bm = bml * 128;
            const int bn = bnl * 128;
            const __half* A = P  + (long)bz * SS * SS + (long)bm * SS;
            const __half* B = Vt + (long)bz * DD * SS + (long)bn * SS;
            mainloop_h(A, B, SS, SS, SS, sbase, tid, lane, wm, wn, acc);

            const float* rs = RS + bz * SS;
            float* C = O + (long)bz * SS * DD;
#pragma unroll
            for (int mt = 0; mt < 4; mt++) {
                const int m0 = bm + wm * 64 + mt * 16 + g;
                const float i0 = 1.0f / __ldg(&rs[m0]);
                const float i1 = 1.0f / __ldg(&rs[m0 + 8]);
#pragma unroll
                for (int nt = 0; nt < 4; nt++) {
                    const int n = bn + wn * 32 + nt * 8 + tg * 2;
                    float2 v0, v1;
                    v0.x = acc[mt][nt][0] * i0;
                    v0.y = acc[mt][nt][1] * i0;
                    v1.x = acc[mt][nt][2] * i1;
                    v1.y = acc[mt][nt][3] * i1;
                    *(float2*)(C + (long)m0 * DD + n)       = v0;
                    *(float2*)(C + (long)(m0 + 8) * DD + n) = v1;
                }
            }
        }
    }
}

extern "C" void kernel_launch(void* const* d_in, const int* in_sizes, int n_in,
                              void* d_out, int out_size)
{
    const float* x  = (const float*)d_in[0];
    const float* y  = (const float*)d_in[1];
    const float* z  = (const float*)d_in[2];
    const float* Wq = (const float*)d_in[3];
    const float* bq = (const float*)d_in[4];
    const float* Wk = (const float*)d_in[5];
    const float* bk = (const float*)d_in[6];
    const float* Wv = (const float*)d_in[7];
    const float* bv = (const float*)d_in[8];
    float* out = (float*)d_out;

    void *pX, *pY, *pZ, *pW, *pQ, *pK, *pV, *pP, *pRS;
    cudaGetSymbolAddress(&pX,  g_X);
    cudaGetSymbolAddress(&pY,  g_Y);
    cudaGetSymbolAddress(&pZ,  g_Z);
    cudaGetSymbolAddress(&pW,  g_W);
    cudaGetSymbolAddress(&pQ,  g_Q);
    cudaGetSymbolAddress(&pK,  g_K);
    cudaGetSymbolAddress(&pV,  g_Vt);
    cudaGetSymbolAddress(&pP,  g_P);
    cudaGetSymbolAddress(&pRS, g_RS);

    int nsm = 148;
    cudaDeviceGetAttribute(&nsm, cudaDevAttrMultiProcessorCount, 0);

    const int SMEMSZ = 3 * 32768;   // 96 KB
    cudaFuncSetAttribute(attn_mega, cudaFuncAttributeMaxDynamicSharedMemorySize, SMEMSZ);

    // 0) conversions + scheduler/RS zeroing
    cvt_all<<<13824, 256>>>((const float4*)x, (const float4*)y, (const float4*)z,
                            (const float4*)Wq, (const float4*)Wk, (const float4*)Wv,
                            (__half*)pX, (__half*)pY, (__half*)pZ, (__half*)pW,
                            (float*)pRS);
    // 1) persistent fused proj + scores + PV
    attn_mega<<<2 * nsm, 256, SMEMSZ>>>((__half*)pX, (__half*)pY, (__half*)pZ,
                                        (__half*)pW, bq, bk, bv,
                                        (__half*)pQ, (__half*)pK, (__half*)pV,
                                        (__half*)pP, (float*)pRS, out);
}